// round 1
// baseline (speedup 1.0000x reference)
#include <cuda_runtime.h>
#include <math.h>

#define B_ 4
#define N_ 2048
#define C_ 1024
#define H_ 16
#define D_ 64
#define M_ (B_*N_)   // 8192

// Scratch (allocation-free rule: device globals)
__device__ float g_q[(size_t)B_*H_*N_*D_];
__device__ float g_k[(size_t)B_*H_*N_*D_];
__device__ float g_v[(size_t)B_*H_*N_*D_];
__device__ float g_att[(size_t)M_*C_];

// C[m, o] = sum_k A[m,k] * W[o,k]  (A: [M x K] row-major, W: [Nout x K] row-major)
// mode 0: scatter epilogue into g_q/g_k/g_v (QKV projection)
// mode 1: A := g_att, add bias, write Cout (output projection)
__global__ void __launch_bounds__(256)
sgemm_abt(const float* __restrict__ A, const float* __restrict__ W,
          const float* __restrict__ bias, float* __restrict__ Cout,
          int K, int mode)
{
    __shared__ float As[16][128];
    __shared__ float Bs[16][128];
    const int tid = threadIdx.x;
    const int m0 = blockIdx.y * 128;
    const int n0 = blockIdx.x * 128;
    const int ty = tid >> 4;      // 0..15
    const int tx = tid & 15;      // 0..15
    if (mode == 1) A = g_att;

    const int K4 = K >> 2;
    const float4* A4 = reinterpret_cast<const float4*>(A);
    const float4* W4 = reinterpret_cast<const float4*>(W);

    float acc[8][8];
    #pragma unroll
    for (int i = 0; i < 8; i++)
        #pragma unroll
        for (int j = 0; j < 8; j++) acc[i][j] = 0.f;

    for (int k0 = 0; k0 < K4; k0 += 4) {   // 16 floats of K per tile
        #pragma unroll
        for (int u = 0; u < 2; u++) {
            int v   = u * 256 + tid;   // 0..511
            int row = v >> 2;          // 0..127
            int kc  = v & 3;           // float4 index within the 16-wide K tile
            float4 fa = A4[(size_t)(m0 + row) * K4 + k0 + kc];
            As[kc*4+0][row] = fa.x; As[kc*4+1][row] = fa.y;
            As[kc*4+2][row] = fa.z; As[kc*4+3][row] = fa.w;
            float4 fw = W4[(size_t)(n0 + row) * K4 + k0 + kc];
            Bs[kc*4+0][row] = fw.x; Bs[kc*4+1][row] = fw.y;
            Bs[kc*4+2][row] = fw.z; Bs[kc*4+3][row] = fw.w;
        }
        __syncthreads();
        #pragma unroll
        for (int kk = 0; kk < 16; kk++) {
            float4 a0 = *(const float4*)&As[kk][ty*4];
            float4 a1 = *(const float4*)&As[kk][64 + ty*4];
            float4 b0 = *(const float4*)&Bs[kk][tx*4];
            float4 b1 = *(const float4*)&Bs[kk][64 + tx*4];
            float af[8] = {a0.x, a0.y, a0.z, a0.w, a1.x, a1.y, a1.z, a1.w};
            float bf[8] = {b0.x, b0.y, b0.z, b0.w, b1.x, b1.y, b1.z, b1.w};
            #pragma unroll
            for (int i = 0; i < 8; i++)
                #pragma unroll
                for (int j = 0; j < 8; j++)
                    acc[i][j] += af[i] * bf[j];
        }
        __syncthreads();
    }

    #pragma unroll
    for (int ih = 0; ih < 2; ih++) {
        #pragma unroll
        for (int i = 0; i < 4; i++) {
            int gm = m0 + ih*64 + ty*4 + i;
            #pragma unroll
            for (int jh = 0; jh < 2; jh++) {
                int gn = n0 + jh*64 + tx*4;
                float4 val;
                val.x = acc[ih*4+i][jh*4+0];
                val.y = acc[ih*4+i][jh*4+1];
                val.z = acc[ih*4+i][jh*4+2];
                val.w = acc[ih*4+i][jh*4+3];
                if (mode == 0) {
                    // o = which*C + h*D + d ; write head-major Q/K/V
                    int which = gn >> 10;
                    int rem   = gn & 1023;
                    int h     = rem >> 6;
                    int d     = rem & 63;
                    int b     = gm >> 11;
                    int nrow  = gm & 2047;
                    float* dst = (which == 0) ? g_q : (which == 1) ? g_k : g_v;
                    *(float4*)&dst[(((size_t)(b*H_ + h))*N_ + nrow)*D_ + d] = val;
                } else {
                    float4 bv = *(const float4*)&bias[gn];
                    val.x += bv.x; val.y += bv.y; val.z += bv.z; val.w += bv.w;
                    *(float4*)&Cout[(size_t)gm * C_ + gn] = val;
                }
            }
        }
    }
}

// Flash-style causal attention: one block = (b,h) x 32-query tile.
// Streams 32-key tiles with online softmax. Writes g_att in [b, n, h*D+d] layout.
__global__ void __launch_bounds__(256)
flash_causal()
{
    __shared__ float Qts[64][33];   // k-major Q (conflict-free Q[k][row] reads)
    __shared__ float Ks[32][68];    // row-major, 16B-aligned rows
    __shared__ float Vs[32][68];
    __shared__ float Ss[32][33];
    __shared__ float m_s[32], l_s[32], alpha_s[32];

    const int tid = threadIdx.x;
    const int bh  = blockIdx.y;          // b*H + h
    const int qb  = blockIdx.x;
    const int qbase = qb * 32;
    const size_t head_off = (size_t)bh * N_ * D_;

    // Load + transpose Q tile
    #pragma unroll
    for (int u = 0; u < 2; u++) {
        int v   = u * 256 + tid;   // 0..511
        int row = v >> 4;          // 0..31
        int c4  = (v & 15) * 4;
        float4 f = *(const float4*)&g_q[head_off + (size_t)(qbase + row)*D_ + c4];
        Qts[c4+0][row] = f.x; Qts[c4+1][row] = f.y;
        Qts[c4+2][row] = f.z; Qts[c4+3][row] = f.w;
    }
    if (tid < 32) { m_s[tid] = -1e30f; l_s[tid] = 0.f; }

    const int orow = tid >> 3;        // 0..31 (O-tile row this thread owns)
    const int oc   = (tid & 7) * 8;   // 8 output dims
    float o_acc[8] = {0.f,0.f,0.f,0.f,0.f,0.f,0.f,0.f};

    const int srow = tid & 31;        // S row
    const int sc0  = (tid >> 5) * 4;  // S col group

    for (int j = 0; j <= qb; j++) {
        __syncthreads();   // previous iter done with Ks/Vs/Ss (and Q ready on iter 0)
        const int kbase = j * 32;
        #pragma unroll
        for (int u = 0; u < 2; u++) {
            int v   = u * 256 + tid;
            int row = v >> 4;
            int c4  = (v & 15) * 4;
            *(float4*)&Ks[row][c4] = *(const float4*)&g_k[head_off + (size_t)(kbase + row)*D_ + c4];
            *(float4*)&Vs[row][c4] = *(const float4*)&g_v[head_off + (size_t)(kbase + row)*D_ + c4];
        }
        __syncthreads();

        // S = (Q K^T) * scale, causal mask
        float a0 = 0.f, a1 = 0.f, a2 = 0.f, a3 = 0.f;
        #pragma unroll
        for (int k4 = 0; k4 < 16; k4++) {
            float q0 = Qts[k4*4+0][srow];
            float q1 = Qts[k4*4+1][srow];
            float q2 = Qts[k4*4+2][srow];
            float q3 = Qts[k4*4+3][srow];
            float4 kv0 = *(const float4*)&Ks[sc0+0][k4*4];
            float4 kv1 = *(const float4*)&Ks[sc0+1][k4*4];
            float4 kv2 = *(const float4*)&Ks[sc0+2][k4*4];
            float4 kv3 = *(const float4*)&Ks[sc0+3][k4*4];
            a0 += q0*kv0.x + q1*kv0.y + q2*kv0.z + q3*kv0.w;
            a1 += q0*kv1.x + q1*kv1.y + q2*kv1.z + q3*kv1.w;
            a2 += q0*kv2.x + q1*kv2.y + q2*kv2.z + q3*kv2.w;
            a3 += q0*kv3.x + q1*kv3.y + q2*kv3.z + q3*kv3.w;
        }
        const int qg = qbase + srow;
        Ss[srow][sc0+0] = (kbase + sc0 + 0 <= qg) ? a0 * 0.125f : -1e30f;
        Ss[srow][sc0+1] = (kbase + sc0 + 1 <= qg) ? a1 * 0.125f : -1e30f;
        Ss[srow][sc0+2] = (kbase + sc0 + 2 <= qg) ? a2 * 0.125f : -1e30f;
        Ss[srow][sc0+3] = (kbase + sc0 + 3 <= qg) ? a3 * 0.125f : -1e30f;
        __syncthreads();

        // Online softmax, 8 threads per row, shuffle reductions within the 8-lane group
        {
            int r  = tid >> 3;
            int cg = (tid & 7) * 4;
            float v0 = Ss[r][cg+0], v1 = Ss[r][cg+1], v2 = Ss[r][cg+2], v3 = Ss[r][cg+3];
            float pm = fmaxf(fmaxf(v0, v1), fmaxf(v2, v3));
            #pragma unroll
            for (int off = 1; off < 8; off <<= 1)
                pm = fmaxf(pm, __shfl_xor_sync(0xffffffffu, pm, off));
            float mold = m_s[r];
            float mnew = fmaxf(mold, pm);
            float p0 = expf(v0 - mnew), p1 = expf(v1 - mnew);
            float p2 = expf(v2 - mnew), p3 = expf(v3 - mnew);
            Ss[r][cg+0] = p0; Ss[r][cg+1] = p1; Ss[r][cg+2] = p2; Ss[r][cg+3] = p3;
            float ps = p0 + p1 + p2 + p3;
            #pragma unroll
            for (int off = 1; off < 8; off <<= 1)
                ps += __shfl_xor_sync(0xffffffffu, ps, off);
            if ((tid & 7) == 0) {
                float alpha = expf(mold - mnew);
                alpha_s[r] = alpha;
                l_s[r] = l_s[r] * alpha + ps;
                m_s[r] = mnew;
            }
        }
        __syncthreads();

        // O = alpha*O + P V
        float al = alpha_s[orow];
        #pragma unroll
        for (int i = 0; i < 8; i++) o_acc[i] *= al;
        #pragma unroll
        for (int kk = 0; kk < 32; kk++) {
            float p = Ss[orow][kk];
            float4 v0 = *(const float4*)&Vs[kk][oc];
            float4 v1 = *(const float4*)&Vs[kk][oc + 4];
            o_acc[0] += p * v0.x; o_acc[1] += p * v0.y;
            o_acc[2] += p * v0.z; o_acc[3] += p * v0.w;
            o_acc[4] += p * v1.x; o_acc[5] += p * v1.y;
            o_acc[6] += p * v1.z; o_acc[7] += p * v1.w;
        }
    }

    float inv = 1.0f / l_s[orow];
    int b = bh >> 4, h = bh & 15;
    size_t outb = ((size_t)(b * N_ + qbase + orow)) * C_ + h * D_ + oc;
    float4 w0, w1;
    w0.x = o_acc[0]*inv; w0.y = o_acc[1]*inv; w0.z = o_acc[2]*inv; w0.w = o_acc[3]*inv;
    w1.x = o_acc[4]*inv; w1.y = o_acc[5]*inv; w1.z = o_acc[6]*inv; w1.w = o_acc[7]*inv;
    *(float4*)&g_att[outb]     = w0;
    *(float4*)&g_att[outb + 4] = w1;
}

extern "C" void kernel_launch(void* const* d_in, const int* in_sizes, int n_in,
                              void* d_out, int out_size)
{
    const float* x      = (const float*)d_in[0];
    const float* qkv_w  = (const float*)d_in[1];
    const float* proj_w = (const float*)d_in[2];
    const float* proj_b = (const float*)d_in[3];
    float* out = (float*)d_out;

    dim3 blk(256);

    // 1) QKV projection with fused head-major scatter
    dim3 g_qkv(3 * C_ / 128, M_ / 128);            // (24, 64)
    sgemm_abt<<<g_qkv, blk>>>(x, qkv_w, nullptr, nullptr, C_, 0);

    // 2) Causal flash attention
    dim3 g_fa(N_ / 32, B_ * H_);                   // (64, 64)
    flash_causal<<<g_fa, blk>>>();

    // 3) Output projection + bias
    dim3 g_proj(C_ / 128, M_ / 128);               // (8, 64)
    sgemm_abt<<<g_proj, blk>>>(nullptr, proj_w, proj_b, out, C_, 1);
}

// round 2
// speedup vs baseline: 22.9170x; 22.9170x over previous
#include <cuda_runtime.h>
#include <cuda_fp16.h>
#include <cstdint>

#define B_ 4
#define N_ 2048
#define C_ 1024
#define H_ 16
#define D_ 64
#define M_ (B_*N_)   // 8192

// ---------------- scratch (device globals; allocation-free rule) ----------------
__device__ __align__(128) __half g_xh   [(size_t)M_*C_];
__device__ __align__(128) __half g_wqkvh[(size_t)3*C_*C_];
__device__ __align__(128) __half g_wprojh[(size_t)C_*C_];
__device__ __align__(128) __half g_qh[(size_t)B_*H_*N_*D_];
__device__ __align__(128) __half g_kh[(size_t)B_*H_*N_*D_];
__device__ __align__(128) __half g_vh[(size_t)B_*H_*N_*D_];
__device__ __align__(128) __half g_atth[(size_t)M_*C_];

// ---------------- small PTX helpers ----------------
__device__ __forceinline__ uint32_t cvta_s(const void* p){
    return (uint32_t)__cvta_generic_to_shared(p);
}
__device__ __forceinline__ void ldsm4(uint32_t& r0, uint32_t& r1, uint32_t& r2, uint32_t& r3, uint32_t a){
    asm volatile("ldmatrix.sync.aligned.m8n8.x4.shared.b16 {%0,%1,%2,%3},[%4];"
                 : "=r"(r0),"=r"(r1),"=r"(r2),"=r"(r3) : "r"(a));
}
__device__ __forceinline__ void ldsm4t(uint32_t& r0, uint32_t& r1, uint32_t& r2, uint32_t& r3, uint32_t a){
    asm volatile("ldmatrix.sync.aligned.m8n8.x4.trans.shared.b16 {%0,%1,%2,%3},[%4];"
                 : "=r"(r0),"=r"(r1),"=r"(r2),"=r"(r3) : "r"(a));
}
__device__ __forceinline__ void mma16816(float* d, const uint32_t* a, const uint32_t* b){
    asm volatile("mma.sync.aligned.m16n8k16.row.col.f32.f16.f16.f32 "
                 "{%0,%1,%2,%3},{%4,%5,%6,%7},{%8,%9},{%0,%1,%2,%3};"
                 : "+f"(d[0]),"+f"(d[1]),"+f"(d[2]),"+f"(d[3])
                 : "r"(a[0]),"r"(a[1]),"r"(a[2]),"r"(a[3]),"r"(b[0]),"r"(b[1]));
}
__device__ __forceinline__ void cp16(uint32_t s, const void* g){
    asm volatile("cp.async.cg.shared.global [%0],[%1],16;" :: "r"(s),"l"(g));
}
__device__ __forceinline__ void cpcommit(){ asm volatile("cp.async.commit_group;"); }
__device__ __forceinline__ void cpwait0(){ asm volatile("cp.async.wait_group 0;"); }

// ---------------- fp32 -> fp16 converter ----------------
__global__ void __launch_bounds__(256)
f2h(const float* __restrict__ src, int n4, int which)
{
    __half* dst = (which==0) ? g_xh : (which==1 ? g_wqkvh : g_wprojh);
    int i = blockIdx.x*256 + threadIdx.x;
    if (i >= n4) return;
    float4 f = ((const float4*)src)[i];
    __half2 h0 = __floats2half2_rn(f.x, f.y);
    __half2 h1 = __floats2half2_rn(f.z, f.w);
    ((__half2*)dst)[i*2]   = h0;
    ((__half2*)dst)[i*2+1] = h1;
}

// ---------------- HGEMM: C[m,o] = sum_k A[m,k] * W[o,k]  (fp16 in, fp32 acc) ----
// mode 0: A=g_xh, W=g_wqkvh, scatter fp16 Q/K/V head-major
// mode 1: A=g_atth, W=g_wprojh, add bias, write fp32 out
__global__ void __launch_bounds__(128)
hgemm(const float* __restrict__ bias, float* __restrict__ out, int mode)
{
    __shared__ __align__(16) __half As[2][128*64];
    __shared__ __align__(16) __half Bs[2][64*64];
    const int tid = threadIdx.x;
    const int w = tid>>5, lane = tid&31;
    const int g = lane>>2, t = lane&3;
    const int m0 = blockIdx.y*128, n0 = blockIdx.x*64;
    const int wm = (w>>1)*64, wn = (w&1)*32;

    const __half* Ap = (mode==0) ? g_xh    : g_atth;
    const __half* Wp = (mode==0) ? g_wqkvh : g_wprojh;

    uint32_t as_b[2] = { cvta_s(As[0]), cvta_s(As[1]) };
    uint32_t bs_b[2] = { cvta_s(Bs[0]), cvta_s(Bs[1]) };

    float acc[4][4][4];
    #pragma unroll
    for (int i=0;i<4;i++)
        #pragma unroll
        for (int jj=0;jj<4;jj++)
            #pragma unroll
            for (int e=0;e<4;e++) acc[i][jj][e] = 0.f;

    auto ldtile = [&](int buf, int kt){
        const __half* a = Ap + (size_t)m0*C_ + kt*64;
        #pragma unroll
        for (int it=0; it<8; it++){
            int idx = it*128 + tid, r = idx>>3, c = idx&7;
            cp16(as_b[buf] + (r<<7) + (((c^(r&7)))<<4), a + (size_t)r*C_ + c*8);
        }
        const __half* bsrc = Wp + (size_t)n0*C_ + kt*64;
        #pragma unroll
        for (int it=0; it<4; it++){
            int idx = it*128 + tid, r = idx>>3, c = idx&7;
            cp16(bs_b[buf] + (r<<7) + (((c^(r&7)))<<4), bsrc + (size_t)r*C_ + c*8);
        }
    };

    ldtile(0, 0); cpcommit();

    for (int kt=0; kt<16; kt++){
        int buf = kt&1;
        cpwait0(); __syncthreads();
        if (kt < 15){ ldtile(buf^1, kt+1); cpcommit(); }

        #pragma unroll
        for (int ks=0; ks<4; ks++){
            uint32_t a[4][4];
            #pragma unroll
            for (int i=0;i<4;i++){
                int row = wm + 16*i + (lane&15);
                uint32_t addr = as_b[buf] + (row<<7) + ((((2*ks + (lane>>4)) ^ (row&7)))<<4);
                ldsm4(a[i][0],a[i][1],a[i][2],a[i][3], addr);
            }
            uint32_t b[4][2];
            #pragma unroll
            for (int p=0;p<2;p++){
                int row = wn + 16*p + ((lane>>4)&1)*8 + (lane&7);
                uint32_t addr = bs_b[buf] + (row<<7) + ((((2*ks + ((lane>>3)&1)) ^ (row&7)))<<4);
                uint32_t r0,r1,r2,r3; ldsm4(r0,r1,r2,r3, addr);
                b[2*p][0]=r0; b[2*p][1]=r1; b[2*p+1][0]=r2; b[2*p+1][1]=r3;
            }
            #pragma unroll
            for (int i=0;i<4;i++)
                #pragma unroll
                for (int jj=0;jj<4;jj++)
                    mma16816(acc[i][jj], a[i], b[jj]);
        }
    }

    if (mode == 0){
        int which = n0 >> 10;
        int h     = (n0 >> 6) & 15;
        int b_    = m0 >> 11;
        __half* dst = (which==0) ? g_qh : (which==1 ? g_kh : g_vh);
        dst += ((size_t)(b_*H_ + h))*N_*D_;
        #pragma unroll
        for (int i=0;i<4;i++){
            int rlo = (m0 & 2047) + wm + 16*i + g;
            #pragma unroll
            for (int jj=0;jj<4;jj++){
                int d = wn + 8*jj + 2*t;
                __half2 lo = __floats2half2_rn(acc[i][jj][0], acc[i][jj][1]);
                __half2 hi = __floats2half2_rn(acc[i][jj][2], acc[i][jj][3]);
                *(__half2*)(dst + (size_t)rlo*D_ + d)     = lo;
                *(__half2*)(dst + (size_t)(rlo+8)*D_ + d) = hi;
            }
        }
    } else {
        #pragma unroll
        for (int i=0;i<4;i++){
            int gm = m0 + wm + 16*i + g;
            #pragma unroll
            for (int jj=0;jj<4;jj++){
                int gn = n0 + wn + 8*jj + 2*t;
                float bx = bias[gn], by = bias[gn+1];
                float2 lo = make_float2(acc[i][jj][0]+bx, acc[i][jj][1]+by);
                float2 hi = make_float2(acc[i][jj][2]+bx, acc[i][jj][3]+by);
                *(float2*)(out + (size_t)gm*C_ + gn)     = lo;
                *(float2*)(out + (size_t)(gm+8)*C_ + gn) = hi;
            }
        }
    }
}

// ---------------- flash attention (fp16 mma, fp32 online softmax) ----------------
// CTA: 4 warps, 64 queries (warp w owns rows 16w..16w+15), 64-key tiles.
__global__ void __launch_bounds__(128)
flash16()
{
    __shared__ __align__(16) __half Qs[64*64];
    __shared__ __align__(16) __half Ks[2][64*64];
    __shared__ __align__(16) __half Vs[2][64*64];

    const int tid = threadIdx.x, w = tid>>5, lane = tid&31;
    const int g = lane>>2, t = lane&3;
    const int qb = blockIdx.x, bh = blockIdx.y;
    const int qbase = qb*64;
    const size_t hoff = (size_t)bh*N_*D_;
    const __half* Qg = g_qh + hoff;
    const __half* Kg = g_kh + hoff;
    const __half* Vg = g_vh + hoff;

    uint32_t qs_b = cvta_s(Qs);
    uint32_t ks_b[2] = { cvta_s(Ks[0]), cvta_s(Ks[1]) };
    uint32_t vs_b[2] = { cvta_s(Vs[0]), cvta_s(Vs[1]) };

    auto ldkv = [&](int buf, int j){
        const __half* ks = Kg + (size_t)j*64*D_;
        const __half* vs = Vg + (size_t)j*64*D_;
        #pragma unroll
        for (int it=0; it<4; it++){
            int idx = it*128 + tid, r = idx>>3, c = idx&7;
            uint32_t off = (r<<7) + (((c^(r&7)))<<4);
            cp16(ks_b[buf] + off, ks + (size_t)r*D_ + c*8);
            cp16(vs_b[buf] + off, vs + (size_t)r*D_ + c*8);
        }
    };

    ldkv(0, 0); cpcommit();

    // Q tile -> swizzled smem (plain vector loads)
    #pragma unroll
    for (int it=0; it<4; it++){
        int idx = it*128 + tid, r = idx>>3, c = idx&7;
        float4 v = *(const float4*)(Qg + (size_t)(qbase+r)*D_ + c*8);
        *(float4*)((char*)Qs + (r<<7) + (((c^(r&7)))<<4)) = v;
    }
    __syncthreads();

    uint32_t qf[4][4];
    #pragma unroll
    for (int ks=0; ks<4; ks++){
        int row = 16*w + (lane&15);
        uint32_t addr = qs_b + (row<<7) + ((((2*ks + (lane>>4)) ^ (row&7)))<<4);
        ldsm4(qf[ks][0],qf[ks][1],qf[ks][2],qf[ks][3], addr);
    }

    float m_lo=-1e30f, m_hi=-1e30f, l_lo=0.f, l_hi=0.f;
    float o[8][4];
    #pragma unroll
    for (int jj=0;jj<8;jj++)
        #pragma unroll
        for (int e=0;e<4;e++) o[jj][e]=0.f;

    const float sc = 0.18033688011112042f;  // (1/sqrt(64)) * log2(e)
    const int qlo = qbase + 16*w + g;
    const int qhi = qlo + 8;

    for (int j=0; j<=qb; j++){
        int buf = j&1;
        cpwait0(); __syncthreads();
        if (j < qb){ ldkv(buf^1, j+1); cpcommit(); }

        // S = Q K^T
        float s[8][4];
        #pragma unroll
        for (int jj=0;jj<8;jj++)
            #pragma unroll
            for (int e=0;e<4;e++) s[jj][e]=0.f;

        #pragma unroll
        for (int ks=0; ks<4; ks++){
            uint32_t kf[8][2];
            #pragma unroll
            for (int p=0;p<4;p++){
                int row = 16*p + ((lane>>4)&1)*8 + (lane&7);
                uint32_t addr = ks_b[buf] + (row<<7) + ((((2*ks + ((lane>>3)&1)) ^ (row&7)))<<4);
                uint32_t r0,r1,r2,r3; ldsm4(r0,r1,r2,r3, addr);
                kf[2*p][0]=r0; kf[2*p][1]=r1; kf[2*p+1][0]=r2; kf[2*p+1][1]=r3;
            }
            #pragma unroll
            for (int jj=0;jj<8;jj++) mma16816(s[jj], qf[ks], kf[jj]);
        }

        // scale + causal mask + online softmax (base 2)
        const bool diag = (j == qb);
        float mt_lo = m_lo, mt_hi = m_hi;
        #pragma unroll
        for (int jj=0;jj<8;jj++){
            int c0 = j*64 + 8*jj + 2*t;
            float z0 = s[jj][0]*sc, z1 = s[jj][1]*sc;
            float z2 = s[jj][2]*sc, z3 = s[jj][3]*sc;
            if (diag){
                if (c0   > qlo) z0 = -1e30f;
                if (c0+1 > qlo) z1 = -1e30f;
                if (c0   > qhi) z2 = -1e30f;
                if (c0+1 > qhi) z3 = -1e30f;
            }
            s[jj][0]=z0; s[jj][1]=z1; s[jj][2]=z2; s[jj][3]=z3;
            mt_lo = fmaxf(mt_lo, fmaxf(z0,z1));
            mt_hi = fmaxf(mt_hi, fmaxf(z2,z3));
        }
        mt_lo = fmaxf(mt_lo, __shfl_xor_sync(0xffffffffu, mt_lo, 1));
        mt_lo = fmaxf(mt_lo, __shfl_xor_sync(0xffffffffu, mt_lo, 2));
        mt_hi = fmaxf(mt_hi, __shfl_xor_sync(0xffffffffu, mt_hi, 1));
        mt_hi = fmaxf(mt_hi, __shfl_xor_sync(0xffffffffu, mt_hi, 2));

        float alpha_lo = exp2f(m_lo - mt_lo);
        float alpha_hi = exp2f(m_hi - mt_hi);
        m_lo = mt_lo; m_hi = mt_hi;

        float sum_lo = 0.f, sum_hi = 0.f;
        uint32_t pf[8][2];
        #pragma unroll
        for (int jj=0;jj<8;jj++){
            float p0 = exp2f(s[jj][0]-m_lo), p1 = exp2f(s[jj][1]-m_lo);
            float p2 = exp2f(s[jj][2]-m_hi), p3 = exp2f(s[jj][3]-m_hi);
            sum_lo += p0+p1; sum_hi += p2+p3;
            __half2 plo = __floats2half2_rn(p0,p1);
            __half2 phi = __floats2half2_rn(p2,p3);
            pf[jj][0] = *(uint32_t*)&plo;
            pf[jj][1] = *(uint32_t*)&phi;
        }
        sum_lo += __shfl_xor_sync(0xffffffffu, sum_lo, 1);
        sum_lo += __shfl_xor_sync(0xffffffffu, sum_lo, 2);
        sum_hi += __shfl_xor_sync(0xffffffffu, sum_hi, 1);
        sum_hi += __shfl_xor_sync(0xffffffffu, sum_hi, 2);
        l_lo = l_lo*alpha_lo + sum_lo;
        l_hi = l_hi*alpha_hi + sum_hi;

        #pragma unroll
        for (int jj=0;jj<8;jj++){
            o[jj][0]*=alpha_lo; o[jj][1]*=alpha_lo;
            o[jj][2]*=alpha_hi; o[jj][3]*=alpha_hi;
        }

        // O += P V
        #pragma unroll
        for (int ks=0; ks<4; ks++){
            uint32_t vf[8][2];
            #pragma unroll
            for (int p=0;p<4;p++){
                int row = 16*ks + ((lane>>3)&1)*8 + (lane&7);
                uint32_t addr = vs_b[buf] + (row<<7) + ((((2*p + (lane>>4)) ^ (row&7)))<<4);
                uint32_t r0,r1,r2,r3; ldsm4t(r0,r1,r2,r3, addr);
                vf[2*p][0]=r0; vf[2*p][1]=r1; vf[2*p+1][0]=r2; vf[2*p+1][1]=r3;
            }
            uint32_t af[4] = { pf[2*ks][0], pf[2*ks][1], pf[2*ks+1][0], pf[2*ks+1][1] };
            #pragma unroll
            for (int jj=0;jj<8;jj++) mma16816(o[jj], af, vf[jj]);
        }
    }

    float inv_lo = 1.f/l_lo, inv_hi = 1.f/l_hi;
    int h = bh & 15, b_ = bh >> 4;
    __half* outp  = g_atth + ((size_t)(b_*N_ + qlo))*C_ + h*D_;
    __half* outp2 = outp + (size_t)8*C_;
    #pragma unroll
    for (int jj=0;jj<8;jj++){
        __half2 lo = __floats2half2_rn(o[jj][0]*inv_lo, o[jj][1]*inv_lo);
        __half2 hi = __floats2half2_rn(o[jj][2]*inv_hi, o[jj][3]*inv_hi);
        *(__half2*)(outp  + 8*jj + 2*t) = lo;
        *(__half2*)(outp2 + 8*jj + 2*t) = hi;
    }
}

// ---------------- launch ----------------
extern "C" void kernel_launch(void* const* d_in, const int* in_sizes, int n_in,
                              void* d_out, int out_size)
{
    const float* x      = (const float*)d_in[0];
    const float* qkv_w  = (const float*)d_in[1];
    const float* proj_w = (const float*)d_in[2];
    const float* proj_b = (const float*)d_in[3];
    float* out = (float*)d_out;

    f2h<<<8192, 256>>>(x,      (M_*C_)/4,      0);
    f2h<<<3072, 256>>>(qkv_w,  (3*C_*C_)/4,    1);
    f2h<<<1024, 256>>>(proj_w, (C_*C_)/4,      2);

    hgemm<<<dim3(3*C_/64, M_/128), 128>>>(nullptr, nullptr, 0);   // QKV + scatter
    flash16<<<dim3(N_/64, B_*H_), 128>>>();                       // causal attention
    hgemm<<<dim3(C_/64, M_/128), 128>>>(proj_b, out, 1);          // out proj + bias
}